// round 1
// baseline (speedup 1.0000x reference)
#include <cuda_runtime.h>
#include <cstdint>

#define PNUM 128
#define MAXBATCH 8192

typedef unsigned long long u64;

__device__ float g_batch_loss[MAXBATCH];

// ---- packed f32x2 helpers (sm_103a) ----
__device__ __forceinline__ u64 pk_add(u64 a, u64 b) {
    u64 r;
    asm("add.rn.f32x2 %0, %1, %2;" : "=l"(r) : "l"(a), "l"(b));
    return r;
}
__device__ __forceinline__ u64 pk_fma(u64 a, u64 b, u64 c) {
    u64 r;
    asm("fma.rn.f32x2 %0, %1, %2, %3;" : "=l"(r) : "l"(a), "l"(b), "l"(c));
    return r;
}
__device__ __forceinline__ u64 pk_pack(float lo, float hi) {
    u64 r;
    asm("mov.b64 %0, {%1, %2};" : "=l"(r) : "f"(lo), "f"(hi));
    return r;
}
__device__ __forceinline__ void pk_unpack(u64 v, float& lo, float& hi) {
    asm("mov.b64 {%0, %1}, %2;" : "=f"(lo), "=f"(hi) : "l"(v));
}

// smoothL1(d) = 0.5*d^2 - 0.5*r^2,  r = max(|d|-1, 0)
// p = point (x,y) packed, ng = negated gt point packed.
__device__ __forceinline__ void evalpair(u64 p, u64 ng, u64& sQ, u64& sR) {
    u64 d = pk_add(p, ng);          // FADD2: d = p - g
    sQ = pk_fma(d, d, sQ);          // FFMA2: sQ += d*d
    float dx, dy;
    pk_unpack(d, dx, dy);
    float tx = fabsf(dx) - 1.0f;    // FADD |dx|, -1  (abs folded into src)
    float ty = fabsf(dy) - 1.0f;
    float rx = fmaxf(tx, 0.0f);     // FMNMX (alu pipe)
    float ry = fmaxf(ty, 0.0f);
    u64 r = pk_pack(rx, ry);
    sR = pk_fma(r, r, sR);          // FFMA2: sR += r*r
}

__global__ __launch_bounds__(PNUM)
void match_kernel(const float* __restrict__ pred0,
                  const float* __restrict__ pred1,
                  const float* __restrict__ gt) {
    __shared__ __align__(16) u64 sp0[PNUM];
    __shared__ __align__(16) u64 sp1[PNUM];
    __shared__ __align__(16) u64 sng[2 * PNUM];
    __shared__ float red[8];

    const int tid = threadIdx.x;
    const int b = blockIdx.x;
    const int base = b * PNUM;

    // Load pred0/pred1 points as 8-byte words; gt negated + duplicated so the
    // cyclic index (j+i)%128 becomes a linear address with immediate offsets.
    sp0[tid] = reinterpret_cast<const u64*>(pred0)[base + tid];
    sp1[tid] = reinterpret_cast<const u64*>(pred1)[base + tid];
    {
        float2 g = reinterpret_cast<const float2*>(gt)[base + tid];
        float2 ng = make_float2(-g.x, -g.y);
        u64 ngu = *reinterpret_cast<u64*>(&ng);
        sng[tid] = ngu;
        sng[tid + PNUM] = ngu;
    }
    __syncthreads();

    // Thread tid handles shift j = tid for both preds.
    const u64* gbase = &sng[tid];
    u64 sQ0 = 0ull, sR0 = 0ull, sQ1 = 0ull, sR1 = 0ull;

#pragma unroll 8
    for (int i = 0; i < PNUM; i += 2) {
        ulonglong2 P0 = *reinterpret_cast<const ulonglong2*>(&sp0[i]);  // LDS.128
        ulonglong2 P1 = *reinterpret_cast<const ulonglong2*>(&sp1[i]);  // LDS.128
        u64 ga = gbase[i];       // LDS.64
        u64 gb = gbase[i + 1];   // LDS.64
        evalpair(P0.x, ga, sQ0, sR0);
        evalpair(P0.y, gb, sQ0, sR0);
        evalpair(P1.x, ga, sQ1, sR1);
        evalpair(P1.y, gb, sQ1, sR1);
    }

    float qx, qy, rx, ry;
    pk_unpack(sQ0, qx, qy);
    pk_unpack(sR0, rx, ry);
    float dis0 = (qx + qy - rx - ry) * (0.5f / PNUM);
    pk_unpack(sQ1, qx, qy);
    pk_unpack(sR1, rx, ry);
    float dis1 = (qx + qy - rx - ry) * (0.5f / PNUM);

    // min over 128 shifts: warp shfl min, then 4 warp partials.
#pragma unroll
    for (int o = 16; o > 0; o >>= 1) {
        dis0 = fminf(dis0, __shfl_xor_sync(0xffffffffu, dis0, o));
        dis1 = fminf(dis1, __shfl_xor_sync(0xffffffffu, dis1, o));
    }
    const int w = tid >> 5;
    if ((tid & 31) == 0) {
        red[w] = dis0;
        red[w + 4] = dis1;
    }
    __syncthreads();
    if (tid == 0) {
        float m0 = fminf(fminf(red[0], red[1]), fminf(red[2], red[3]));
        float m1 = fminf(fminf(red[4], red[5]), fminf(red[6], red[7]));
        g_batch_loss[b] = m0 + m1;
    }
}

__global__ void reduce_kernel(float* __restrict__ out, int nbatch) {
    __shared__ float sred[32];
    const int tid = threadIdx.x;
    float acc = 0.0f;
    for (int i = tid; i < nbatch; i += 1024)
        acc += g_batch_loss[i];
#pragma unroll
    for (int o = 16; o > 0; o >>= 1)
        acc += __shfl_xor_sync(0xffffffffu, acc, o);
    if ((tid & 31) == 0) sred[tid >> 5] = acc;
    __syncthreads();
    if (tid < 32) {
        float v = sred[tid];
#pragma unroll
        for (int o = 16; o > 0; o >>= 1)
            v += __shfl_xor_sync(0xffffffffu, v, o);
        if (tid == 0) out[0] = v * (0.5f / (float)nbatch);
    }
}

extern "C" void kernel_launch(void* const* d_in, const int* in_sizes, int n_in,
                              void* d_out, int out_size) {
    const float* pred0 = (const float*)d_in[0];
    const float* pred1 = (const float*)d_in[1];
    const float* gt    = (const float*)d_in[2];
    int nbatch = in_sizes[0] / (PNUM * 2);
    if (nbatch > MAXBATCH) nbatch = MAXBATCH;

    match_kernel<<<nbatch, PNUM>>>(pred0, pred1, gt);
    reduce_kernel<<<1, 1024>>>((float*)d_out, nbatch);
}

// round 2
// speedup vs baseline: 1.6902x; 1.6902x over previous
#include <cuda_runtime.h>
#include <cstdint>

#define PNUM 128
#define MAXBATCH 8192

typedef unsigned long long u64;

__device__ float g_batch_loss[MAXBATCH];

// ---- packed f32x2 helpers (sm_103a) ----
__device__ __forceinline__ u64 pk_add(u64 a, u64 b) {
    u64 r;
    asm("add.rn.f32x2 %0, %1, %2;" : "=l"(r) : "l"(a), "l"(b));
    return r;
}
__device__ __forceinline__ u64 pk_fma(u64 a, u64 b, u64 c) {
    u64 r;
    asm("fma.rn.f32x2 %0, %1, %2, %3;" : "=l"(r) : "l"(a), "l"(b), "l"(c));
    return r;
}
__device__ __forceinline__ u64 pk_pack(float lo, float hi) {
    u64 r;
    asm("mov.b64 %0, {%1, %2};" : "=l"(r) : "f"(lo), "f"(hi));
    return r;
}
__device__ __forceinline__ void pk_unpack(u64 v, float& lo, float& hi) {
    asm("mov.b64 {%0, %1}, %2;" : "=f"(lo), "=f"(hi) : "l"(v));
}

// smoothL1(d) = 0.5*d^2 - 0.5*m^2 + m - 0.5,  m = max(|d|, 1)
//   |d| <  1: 0.5d^2 - 0.5 + 1 - 0.5 = 0.5d^2           (m = 1)
//   |d| >= 1: 0.5d^2 - 0.5d^2 + |d| - 0.5 = |d| - 0.5   (m = |d|)
// Per pair-eval: FADD2(d), FFMA2(Q), FFMA2(M2), FADD2(M) on fma pipe;
// 2x FMNMX (abs as free src modifier) on alu pipe.
__device__ __forceinline__ void evalpair(u64 p, u64 ng, u64& sQ, u64& sM2, u64& sM) {
    u64 d = pk_add(p, ng);          // FADD2: d = p - g
    sQ = pk_fma(d, d, sQ);          // FFMA2: sQ += d*d
    float dx, dy;
    pk_unpack(d, dx, dy);           // reg-pair halves (no real MOV expected)
    float mx = fmaxf(fabsf(dx), 1.0f);  // FMNMX m, |d|, 1.0  (alu pipe)
    float my = fmaxf(fabsf(dy), 1.0f);
    u64 m = pk_pack(mx, my);
    sM2 = pk_fma(m, m, sM2);        // FFMA2: sM2 += m*m
    sM  = pk_add(sM, m);            // FADD2: sM += m
}

__global__ __launch_bounds__(PNUM)
void match_kernel(const float* __restrict__ pred0,
                  const float* __restrict__ pred1,
                  const float* __restrict__ gt) {
    __shared__ __align__(16) u64 sp0[PNUM];
    __shared__ __align__(16) u64 sp1[PNUM];
    __shared__ __align__(16) u64 sng[2 * PNUM];
    __shared__ float red[8];

    const int tid = threadIdx.x;
    const int b = blockIdx.x;
    const int base = b * PNUM;

    // pred points as 8-byte words; gt negated + duplicated so the cyclic
    // index (j+i)%128 becomes a linear address.
    sp0[tid] = reinterpret_cast<const u64*>(pred0)[base + tid];
    sp1[tid] = reinterpret_cast<const u64*>(pred1)[base + tid];
    {
        float2 g = reinterpret_cast<const float2*>(gt)[base + tid];
        float2 ng = make_float2(-g.x, -g.y);
        u64 ngu = *reinterpret_cast<u64*>(&ng);
        sng[tid] = ngu;
        sng[tid + PNUM] = ngu;
    }
    __syncthreads();

    // Thread tid handles shift j = tid for both preds.
    const u64* gbase = &sng[tid];
    u64 sQ0 = 0ull, sM20 = 0ull, sM0 = 0ull;
    u64 sQ1 = 0ull, sM21 = 0ull, sM1 = 0ull;

#pragma unroll 16
    for (int i = 0; i < PNUM; i += 2) {
        ulonglong2 P0 = *reinterpret_cast<const ulonglong2*>(&sp0[i]);  // LDS.128 bcast
        ulonglong2 P1 = *reinterpret_cast<const ulonglong2*>(&sp1[i]);  // LDS.128 bcast
        u64 ga = gbase[i];       // LDS.64 conflict-free
        u64 gb = gbase[i + 1];   // LDS.64
        evalpair(P0.x, ga, sQ0, sM20, sM0);
        evalpair(P0.y, gb, sQ0, sM20, sM0);
        evalpair(P1.x, ga, sQ1, sM21, sM1);
        evalpair(P1.y, gb, sQ1, sM21, sM1);
    }

    // dis = (0.5*(Q - M2) + M - PNUM*... ) / PNUM
    // constant term: 256 pair-terms * (-0.5) = -128 per shift
    float qx, qy, m2x, m2y, mx, my;
    pk_unpack(sQ0, qx, qy);
    pk_unpack(sM20, m2x, m2y);
    pk_unpack(sM0, mx, my);
    float dis0 = (0.5f * ((qx + qy) - (m2x + m2y)) + (mx + my) - 128.0f) * (1.0f / PNUM);
    pk_unpack(sQ1, qx, qy);
    pk_unpack(sM21, m2x, m2y);
    pk_unpack(sM1, mx, my);
    float dis1 = (0.5f * ((qx + qy) - (m2x + m2y)) + (mx + my) - 128.0f) * (1.0f / PNUM);

    // min over 128 shifts: warp shfl min, then 4 warp partials.
#pragma unroll
    for (int o = 16; o > 0; o >>= 1) {
        dis0 = fminf(dis0, __shfl_xor_sync(0xffffffffu, dis0, o));
        dis1 = fminf(dis1, __shfl_xor_sync(0xffffffffu, dis1, o));
    }
    const int w = tid >> 5;
    if ((tid & 31) == 0) {
        red[w] = dis0;
        red[w + 4] = dis1;
    }
    __syncthreads();
    if (tid == 0) {
        float m0 = fminf(fminf(red[0], red[1]), fminf(red[2], red[3]));
        float m1 = fminf(fminf(red[4], red[5]), fminf(red[6], red[7]));
        g_batch_loss[b] = m0 + m1;
    }
}

__global__ void reduce_kernel(float* __restrict__ out, int nbatch) {
    __shared__ float sred[32];
    const int tid = threadIdx.x;
    float acc = 0.0f;
    for (int i = tid; i < nbatch; i += 1024)
        acc += g_batch_loss[i];
#pragma unroll
    for (int o = 16; o > 0; o >>= 1)
        acc += __shfl_xor_sync(0xffffffffu, acc, o);
    if ((tid & 31) == 0) sred[tid >> 5] = acc;
    __syncthreads();
    if (tid < 32) {
        float v = sred[tid];
#pragma unroll
        for (int o = 16; o > 0; o >>= 1)
            v += __shfl_xor_sync(0xffffffffu, v, o);
        if (tid == 0) out[0] = v * (0.5f / (float)nbatch);
    }
}

extern "C" void kernel_launch(void* const* d_in, const int* in_sizes, int n_in,
                              void* d_out, int out_size) {
    const float* pred0 = (const float*)d_in[0];
    const float* pred1 = (const float*)d_in[1];
    const float* gt    = (const float*)d_in[2];
    int nbatch = in_sizes[0] / (PNUM * 2);
    if (nbatch > MAXBATCH) nbatch = MAXBATCH;

    match_kernel<<<nbatch, PNUM>>>(pred0, pred1, gt);
    reduce_kernel<<<1, 1024>>>((float*)d_out, nbatch);
}